// round 16
// baseline (speedup 1.0000x reference)
#include <cuda_runtime.h>
#include <cuda_bf16.h>
#include <cstdint>

#define BATCH 16
#define CH    256
#define SEQ   2048
#define HID   256
#define G3    768
#define M_ROWS (BATCH*SEQ)

typedef unsigned long long ull;
typedef __nv_bfloat16 bf16;

__device__ __forceinline__ ull pack2(float x, float y) {
    ull r; asm("mov.b64 %0,{%1,%2};" : "=l"(r) : "f"(x), "f"(y)); return r;
}
__device__ __forceinline__ void unpack2(ull v, float& x, float& y) {
    asm("mov.b64 {%0,%1},%2;" : "=f"(x), "=f"(y) : "l"(v));
}
__device__ __forceinline__ ull fma2(ull a, ull b, ull c) {
    ull d; asm("fma.rn.f32x2 %0,%1,%2,%3;" : "=l"(d) : "l"(a), "l"(b), "l"(c)); return d;
}
__device__ __forceinline__ float fsig(float x) {
    return __fdividef(1.f, 1.f + __expf(-x));
}
__device__ __forceinline__ float ftanh(float x) {
    float t = __expf(-2.f * fabsf(x));
    return copysignf(__fdividef(1.f - t, 1.f + t), x);
}
static __device__ __forceinline__ uint32_t smem_u32(const void* p) {
    uint32_t a;
    asm("{ .reg .u64 t; cvta.to.shared.u64 t, %1; cvt.u32.u64 %0, t; }"
        : "=r"(a) : "l"(p));
    return a;
}
__device__ __forceinline__ void mbar_wait_cta(uint32_t addr, uint32_t parity) {
    asm volatile(
        "{\n\t.reg .pred P;\n\t"
        "LW_%=:\n\t"
        "mbarrier.try_wait.parity.acquire.cta.shared::cta.b64 P, [%0], %1, 0x989680;\n\t"
        "@!P bra LW_%=;\n\t}"
        :: "r"(addr), "r"(parity) : "memory");
}

// ----------------------------- scratch -------------------------------------
__device__ float g_gi  [(size_t)2 * BATCH * SEQ * G3];
__device__ float g_bufA[(size_t)BATCH * SEQ * 2 * HID];   // also bf16 hi/lo halves
__device__ float g_bufB[(size_t)BATCH * SEQ * 2 * HID];
__device__ bf16  g_Ahi[(size_t)M_ROWS * 512];
__device__ bf16  g_Alo[(size_t)M_ROWS * 512];
__device__ bf16  g_Bhi[(size_t)2 * G3 * 512];
__device__ bf16  g_Blo[(size_t)2 * G3 * 512];

// ----------------------------- transpose + bf16 split ----------------------
__global__ void transpose_split_k(const float* __restrict__ src,
                                  bf16* __restrict__ hi, bf16* __restrict__ lo,
                                  int D1, int D2)
{
    __shared__ float tile[32][33];
    const int b  = blockIdx.z;
    const int j0 = blockIdx.x * 32;
    const int i0 = blockIdx.y * 32;
    const float* s = src + (size_t)b * D1 * D2;
    #pragma unroll
    for (int r = 0; r < 32; r += 8)
        tile[threadIdx.y + r][threadIdx.x] =
            s[(size_t)(i0 + threadIdx.y + r) * D2 + j0 + threadIdx.x];
    __syncthreads();
    #pragma unroll
    for (int r = 0; r < 32; r += 8) {
        float v = tile[threadIdx.x][threadIdx.y + r];
        bf16 h = __float2bfloat16_rn(v);
        size_t idx = (size_t)b * D1 * D2 + (size_t)(j0 + threadIdx.y + r) * D1
                   + i0 + threadIdx.x;
        hi[idx] = h;
        lo[idx] = __float2bfloat16_rn(v - __bfloat162float(h));
    }
}

// ----------------------------- fp32 -> (hi, lo) bf16 split (weights) -------
__global__ void split_k(const float* __restrict__ in,
                        bf16* __restrict__ hi, bf16* __restrict__ lo, int n4)
{
    int i = blockIdx.x * 256 + threadIdx.x;
    if (i >= n4) return;
    float4 v = ((const float4*)in)[i];
    bf16 h0 = __float2bfloat16_rn(v.x);
    bf16 h1 = __float2bfloat16_rn(v.y);
    bf16 h2 = __float2bfloat16_rn(v.z);
    bf16 h3 = __float2bfloat16_rn(v.w);
    __nv_bfloat162* hp = (__nv_bfloat162*)hi;
    __nv_bfloat162* lp = (__nv_bfloat162*)lo;
    hp[i*2]   = __nv_bfloat162(h0, h1);
    hp[i*2+1] = __nv_bfloat162(h2, h3);
    lp[i*2]   = __nv_bfloat162(__float2bfloat16_rn(v.x - __bfloat162float(h0)),
                               __float2bfloat16_rn(v.y - __bfloat162float(h1)));
    lp[i*2+1] = __nv_bfloat162(__float2bfloat16_rn(v.z - __bfloat162float(h2)),
                               __float2bfloat16_rn(v.w - __bfloat162float(h3)));
}

// ----------------------------- bf16-split mma.sync GEMM (R13 winner) -------
// single-buffered smem, cp.async.cg loads; grid.z selects fwd/bwd weights.
// transout: write C transposed as (B, N, SEQ) for the final output.
#define KP 72
#define TILE_ELE (128 * KP)
#define TBYTES   (TILE_ELE * 2)
#define GEMM_SMEM (4 * TBYTES)

__device__ __forceinline__ void cp16(uint32_t s, const void* g) {
    asm volatile("cp.async.cg.shared.global [%0], [%1], 16;" :: "r"(s), "l"(g));
}
__device__ __forceinline__ void ldsm_x4(uint32_t a, uint32_t* r) {
    asm volatile("ldmatrix.sync.aligned.m8n8.x4.shared.b16 {%0,%1,%2,%3}, [%4];"
        : "=r"(r[0]), "=r"(r[1]), "=r"(r[2]), "=r"(r[3]) : "r"(a));
}
__device__ __forceinline__ void ldsm_x2(uint32_t a, uint32_t* r) {
    asm volatile("ldmatrix.sync.aligned.m8n8.x2.shared.b16 {%0,%1}, [%2];"
        : "=r"(r[0]), "=r"(r[1]) : "r"(a));
}
__device__ __forceinline__ void mma16816(float* c, const uint32_t* a, const uint32_t* b) {
    asm volatile(
        "mma.sync.aligned.m16n8k16.row.col.f32.bf16.bf16.f32 "
        "{%0,%1,%2,%3}, {%4,%5,%6,%7}, {%8,%9}, {%0,%1,%2,%3};"
        : "+f"(c[0]), "+f"(c[1]), "+f"(c[2]), "+f"(c[3])
        : "r"(a[0]), "r"(a[1]), "r"(a[2]), "r"(a[3]), "r"(b[0]), "r"(b[1]));
}

__global__ void __launch_bounds__(256)
gemm_mma(const bf16* __restrict__ Ahi, const bf16* __restrict__ Alo,
         const bf16* __restrict__ BhiBase, const bf16* __restrict__ BloBase,
         const float* __restrict__ bias_f, const float* __restrict__ bias_b,
         float* __restrict__ C, bf16* __restrict__ Chi, bf16* __restrict__ Clo,
         int N, int K, int relu, int transout)
{
    extern __shared__ __align__(16) bf16 sm[];
    const int tid  = threadIdx.x;
    const int wid  = tid >> 5, lane = tid & 31;
    const int mw   = wid & 1,  nw   = wid >> 1;
    const int z    = blockIdx.z;
    const bf16* Bhi = BhiBase + (size_t)z * N * K;
    const bf16* Blo = BloBase + (size_t)z * N * K;
    const float* bias = z ? bias_b : bias_f;
    float* Cz = C ? (C + (size_t)z * M_ROWS * N) : nullptr;
    const size_t arow = (size_t)blockIdx.y * 128;
    const size_t brow = (size_t)blockIdx.x * 128;
    const uint32_t sb = smem_u32(sm);

    const int a_r = lane & 15, a_k = (lane >> 4) << 3;
    const int b_r = lane & 7,  b_k = ((lane >> 3) & 1) << 3;

    float acc[4][4][4];
    #pragma unroll
    for (int i = 0; i < 4; i++)
        #pragma unroll
        for (int j = 0; j < 4; j++)
            #pragma unroll
            for (int c = 0; c < 4; c++) acc[i][j][c] = 0.f;

    const int row  = tid >> 1;
    const int half = (tid & 1) * 32;
    const uint32_t s_off = (uint32_t)((row * KP + half) * 2);

    for (int kt = 0; kt < K; kt += 64) {
        if (kt) __syncthreads();   // previous tile fully consumed
        const bf16* gA0 = Ahi + (arow + row) * (size_t)K + kt + half;
        const bf16* gA1 = Alo + (arow + row) * (size_t)K + kt + half;
        const bf16* gB0 = Bhi + (brow + row) * (size_t)K + kt + half;
        const bf16* gB1 = Blo + (brow + row) * (size_t)K + kt + half;
        const uint32_t s0 = sb + s_off;
        #pragma unroll
        for (int q = 0; q < 4; q++) {
            cp16(s0 +              q * 16, gA0 + q * 8);
            cp16(s0 +     TBYTES + q * 16, gA1 + q * 8);
            cp16(s0 + 2 * TBYTES + q * 16, gB0 + q * 8);
            cp16(s0 + 3 * TBYTES + q * 16, gB1 + q * 8);
        }
        asm volatile("cp.async.commit_group;" ::: "memory");
        asm volatile("cp.async.wait_group 0;" ::: "memory");
        __syncthreads();

        #pragma unroll
        for (int ks = 0; ks < 4; ks++) {
            const int k0 = ks * 16;
            uint32_t ah[4][4], al[4][4], bh[4][2], bl[4][2];
            #pragma unroll
            for (int i = 0; i < 4; i++) {
                uint32_t ao = sb + (uint32_t)(((mw * 64 + i * 16 + a_r) * KP + k0 + a_k) * 2);
                ldsm_x4(ao, ah[i]);
                ldsm_x4(ao + TBYTES, al[i]);
            }
            #pragma unroll
            for (int j = 0; j < 4; j++) {
                uint32_t bo = sb + (uint32_t)(2 * TBYTES + ((nw * 32 + j * 8 + b_r) * KP + k0 + b_k) * 2);
                ldsm_x2(bo, bh[j]);
                ldsm_x2(bo + TBYTES, bl[j]);
            }
            #pragma unroll
            for (int i = 0; i < 4; i++)
                #pragma unroll
                for (int j = 0; j < 4; j++) {
                    mma16816(acc[i][j], ah[i], bh[j]);
                    mma16816(acc[i][j], ah[i], bl[j]);
                    mma16816(acc[i][j], al[i], bh[j]);
                }
        }
    }

    const int g = lane >> 2, t = lane & 3;
    const int n_base = blockIdx.x * 128 + nw * 32;
    #pragma unroll
    for (int i = 0; i < 4; i++) {
        const size_t r0 = arow + (size_t)(mw * 64 + i * 16 + g);
        #pragma unroll
        for (int j = 0; j < 4; j++) {
            const int col = n_base + j * 8 + t * 2;
            const float b0 = bias[col], b1 = bias[col + 1];
            float v0 = acc[i][j][0] + b0, v1 = acc[i][j][1] + b1;
            float v2 = acc[i][j][2] + b0, v3 = acc[i][j][3] + b1;
            if (relu) {
                v0 = fmaxf(v0, 0.f); v1 = fmaxf(v1, 0.f);
                v2 = fmaxf(v2, 0.f); v3 = fmaxf(v3, 0.f);
            }
            if (Chi) {
                bf16 h0 = __float2bfloat16_rn(v0), h1 = __float2bfloat16_rn(v1);
                bf16 h2 = __float2bfloat16_rn(v2), h3 = __float2bfloat16_rn(v3);
                *(__nv_bfloat162*)&Chi[r0 * N + col] = __nv_bfloat162(h0, h1);
                *(__nv_bfloat162*)&Chi[(r0 + 8) * N + col] = __nv_bfloat162(h2, h3);
                *(__nv_bfloat162*)&Clo[r0 * N + col] = __nv_bfloat162(
                    __float2bfloat16_rn(v0 - __bfloat162float(h0)),
                    __float2bfloat16_rn(v1 - __bfloat162float(h1)));
                *(__nv_bfloat162*)&Clo[(r0 + 8) * N + col] = __nv_bfloat162(
                    __float2bfloat16_rn(v2 - __bfloat162float(h2)),
                    __float2bfloat16_rn(v3 - __bfloat162float(h3)));
            } else if (transout) {
                // token r0 = b*SEQ + l ; write d_out[(b*N + col)*SEQ + l]
                const size_t bb = r0 >> 11;           // SEQ = 2048
                const size_t l  = r0 & 2047;
                const size_t r1 = r0 + 8;
                const size_t bb2 = r1 >> 11;
                const size_t l2  = r1 & 2047;
                Cz[(bb * N + col)     * (size_t)SEQ + l ] = v0;
                Cz[(bb * N + col + 1) * (size_t)SEQ + l ] = v1;
                Cz[(bb2 * N + col)    * (size_t)SEQ + l2] = v2;
                Cz[(bb2 * N + col + 1)* (size_t)SEQ + l2] = v3;
            } else {
                *(float2*)&Cz[r0 * N + col]       = make_float2(v0, v1);
                *(float2*)&Cz[(r0 + 8) * N + col] = make_float2(v2, v3);
            }
        }
    }
}

// ----------------------------- GRU scan (R10 winner, verbatim — FROZEN) ----
#define SPLIT 4
#define STH   384

__global__ void __launch_bounds__(STH, 1) __cluster_dims__(SPLIT, 1, 1)
scan_kernel(const float* __restrict__ gi,
            const float* __restrict__ whh_f, const float* __restrict__ bhh_f,
            const float* __restrict__ whh_b, const float* __restrict__ bhh_b,
            float* __restrict__ out, bf16* __restrict__ ohi, bf16* __restrict__ olo)
{
    const int ci    = blockIdx.x;
    const int chain = blockIdx.y;
    const int b     = chain & (BATCH - 1);
    const int dir   = chain >> 4;
    const float* whh = dir ? whh_b : whh_f;
    const float* bhh = dir ? bhh_b : bhh_f;
    const float* giB = gi + ((size_t)dir * BATCH + b) * (size_t)SEQ * G3;
    const size_t obase = (size_t)b * SEQ * (2 * HID) + dir * HID;

    const int tid  = threadIdx.x;
    const int g    = tid / 192;
    const int o    = tid % 192;
    const int gate = o >> 6;
    const int jl   = o & 63;
    const int row  = gate * HID + ci * 64 + jl;
    const int gu   = ci * 64 + jl;

    __shared__ __align__(16) float hbuf[2][HID];
    __shared__ float part[STH];
    __shared__ __align__(8) ull mbar[2];

    ull wreg[64];
    {
        const ull* wp = (const ull*)(whh + (size_t)row * HID + g * 128);
        #pragma unroll
        for (int i = 0; i < 64; i++) wreg[i] = wp[i];
    }
    const float bias = (g == 0) ? bhh[row] : 0.f;

    const uint32_t hb0 = smem_u32(&hbuf[0][0]);
    const uint32_t mb0 = smem_u32(&mbar[0]);

    if (tid == 0) {
        asm volatile("mbarrier.init.shared.b64 [%0], 1;" :: "r"(mb0)     : "memory");
        asm volatile("mbarrier.init.shared.b64 [%0], 1;" :: "r"(mb0 + 8) : "memory");
        asm volatile("mbarrier.arrive.expect_tx.shared.b64 _, [%0], 1024;" :: "r"(mb0)     : "memory");
        asm volatile("mbarrier.arrive.expect_tx.shared.b64 _, [%0], 1024;" :: "r"(mb0 + 8) : "memory");
    }
    for (int i = tid; i < 2 * HID; i += STH) (&hbuf[0][0])[i] = 0.f;
    __syncthreads();
    asm volatile("barrier.cluster.arrive.aligned;" ::: "memory");
    asm volatile("barrier.cluster.wait.aligned;"   ::: "memory");

    uint32_t rh0[4], rh1[4], rm0[4], rm1[4];
    if (tid < 64) {
        const uint32_t d0 = hb0 + (uint32_t)(gu * 4);
        const uint32_t d1 = hb0 + (uint32_t)((HID + gu) * 4);
        #pragma unroll
        for (int peer = 0; peer < SPLIT; peer++) {
            asm volatile("mapa.shared::cluster.u32 %0, %1, %2;" : "=r"(rh0[peer]) : "r"(d0), "r"(peer));
            asm volatile("mapa.shared::cluster.u32 %0, %1, %2;" : "=r"(rh1[peer]) : "r"(d1), "r"(peer));
            asm volatile("mapa.shared::cluster.u32 %0, %1, %2;" : "=r"(rm0[peer]) : "r"(mb0), "r"(peer));
            asm volatile("mapa.shared::cluster.u32 %0, %1, %2;" : "=r"(rm1[peer]) : "r"(mb0 + 8), "r"(peer));
        }
    }

    float hreg = 0.f;
    float p_r = 0.f, p_z = 0.f, p_n = 0.f;
    if (tid < 64) {
        const float* gp = giB + (size_t)(dir ? SEQ - 1 : 0) * G3 + gu;
        p_r = __ldg(gp); p_z = __ldg(gp + HID); p_n = __ldg(gp + 2 * HID);
    }

    int ph0 = 0, ph1 = 0;
    for (int s = 0; s < SEQ; s++) {
        const int t = dir ? (SEQ - 1 - s) : s;
        const int p = s & 1;

        if (s > 0) {
            const uint32_t mwadr = mb0 + (uint32_t)(p * 8);
            const uint32_t par = p ? (uint32_t)ph1 : (uint32_t)ph0;
            mbar_wait_cta(mwadr, par);
            if (p) ph1 ^= 1; else ph0 ^= 1;
            if (tid == 0 && s + 2 < SEQ)
                asm volatile("mbarrier.arrive.expect_tx.shared.b64 _, [%0], 1024;"
                             :: "r"(mwadr) : "memory");
        }

        const float gi_r = p_r, gi_z = p_z, gi_n = p_n;
        if (tid < 64 && s + 1 < SEQ) {
            const int tn = dir ? (SEQ - 2 - s) : (s + 1);
            const float* gp = giB + (size_t)tn * G3 + gu;
            p_r = __ldg(gp); p_z = __ldg(gp + HID); p_n = __ldg(gp + 2 * HID);
        }

        ull acc0 = pack2(bias, 0.f);
        ull acc1 = 0ull;
        const ulonglong2* h2 = (const ulonglong2*)&hbuf[p][g * 128];
        #pragma unroll
        for (int kk = 0; kk < 32; kk++) {
            ulonglong2 hv = h2[kk];
            acc0 = fma2(wreg[2*kk],     hv.x, acc0);
            acc1 = fma2(wreg[2*kk + 1], hv.y, acc1);
        }
        float aa, bb, cc, dd;
        unpack2(acc0, aa, bb); unpack2(acc1, cc, dd);
        part[tid] = (aa + cc) + (bb + dd);
        __syncthreads();

        if (tid < 64) {
            const float gh_r = part[tid]       + part[192 + tid];
            const float gh_z = part[64 + tid]  + part[256 + tid];
            const float gh_n = part[128 + tid] + part[320 + tid];
            const float r = fsig(gi_r + gh_r);
            const float z = fsig(gi_z + gh_z);
            const float n = ftanh(gi_n + r * gh_n);
            hreg = n + z * (hreg - n);
            if (s + 1 < SEQ) {
                #pragma unroll
                for (int peer = 0; peer < SPLIT; peer++) {
                    const uint32_t ra = p ? rh0[peer] : rh1[peer];
                    const uint32_t rm = p ? rm0[peer] : rm1[peer];
                    asm volatile(
                        "st.async.shared::cluster.mbarrier::complete_tx::bytes.f32 [%0], %1, [%2];"
                        :: "r"(ra), "f"(hreg), "r"(rm) : "memory");
                }
            }
            const size_t idx = obase + (size_t)t * (2 * HID) + gu;
            if (ohi) {
                bf16 h = __float2bfloat16_rn(hreg);
                ohi[idx] = h;
                olo[idx] = __float2bfloat16_rn(hreg - __bfloat162float(h));
            } else {
                out[idx] = hreg;
            }
        }
    }
}

// ----------------------------- sum dirs + LayerNorm (bf16 split out) -------
__global__ void sum_ln_kernel(const float* __restrict__ in,
                              const float* __restrict__ gw,
                              const float* __restrict__ bw,
                              bf16* __restrict__ ohi, bf16* __restrict__ olo)
{
    const int lane = threadIdx.x & 31;
    const size_t row = (size_t)blockIdx.x * 8 + (threadIdx.x >> 5);
    const float* r = in + row * 512;
    float v[8]; float s = 0.f, s2 = 0.f;
    #pragma unroll
    for (int i = 0; i < 8; i++) {
        int c = i * 32 + lane;
        v[i] = r[c] + r[256 + c];
        s += v[i]; s2 += v[i] * v[i];
    }
    #pragma unroll
    for (int off = 16; off; off >>= 1) {
        s  += __shfl_xor_sync(~0u, s,  off);
        s2 += __shfl_xor_sync(~0u, s2, off);
    }
    const float mu  = s * (1.f / 256.f);
    const float var = s2 * (1.f / 256.f) - mu * mu;
    const float inv = rsqrtf(var + 1e-5f);
    #pragma unroll
    for (int i = 0; i < 8; i++) {
        int c = i * 32 + lane;
        float y = (v[i] - mu) * inv * gw[c] + bw[c];
        bf16 h = __float2bfloat16_rn(y);
        ohi[row * 256 + c] = h;
        olo[row * 256 + c] = __float2bfloat16_rn(y - __bfloat162float(h));
    }
}

// ----------------------------- orchestration -------------------------------
extern "C" void kernel_launch(void* const* d_in, const int* in_sizes, int n_in,
                              void* d_out, int out_size)
{
    (void)in_sizes; (void)n_in; (void)out_size;
    const float* x      = (const float*)d_in[0];
    const float* w_ih0f = (const float*)d_in[1];
    const float* w_hh0f = (const float*)d_in[2];
    const float* b_ih0f = (const float*)d_in[3];
    const float* b_hh0f = (const float*)d_in[4];
    const float* w_ih0b = (const float*)d_in[5];
    const float* w_hh0b = (const float*)d_in[6];
    const float* b_ih0b = (const float*)d_in[7];
    const float* b_hh0b = (const float*)d_in[8];
    const float* w_ih1f = (const float*)d_in[9];
    const float* w_hh1f = (const float*)d_in[10];
    const float* b_ih1f = (const float*)d_in[11];
    const float* b_hh1f = (const float*)d_in[12];
    const float* w_ih1b = (const float*)d_in[13];
    const float* w_hh1b = (const float*)d_in[14];
    const float* b_ih1b = (const float*)d_in[15];
    const float* b_hh1b = (const float*)d_in[16];
    const float* ln_g   = (const float*)d_in[17];
    const float* ln_b   = (const float*)d_in[18];
    const float* w1     = (const float*)d_in[19];
    const float* b1     = (const float*)d_in[20];
    const float* w2     = (const float*)d_in[21];
    const float* b2     = (const float*)d_in[22];

    float *gi, *bufA, *bufB;
    bf16 *Ahi, *Alo, *Bhi, *Blo;
    cudaGetSymbolAddress((void**)&gi,   g_gi);
    cudaGetSymbolAddress((void**)&bufA, g_bufA);
    cudaGetSymbolAddress((void**)&bufB, g_bufB);
    cudaGetSymbolAddress((void**)&Ahi,  g_Ahi);
    cudaGetSymbolAddress((void**)&Alo,  g_Alo);
    cudaGetSymbolAddress((void**)&Bhi,  g_Bhi);
    cudaGetSymbolAddress((void**)&Blo,  g_Blo);

    bf16* bufA_hi = (bf16*)bufA;
    bf16* bufA_lo = bufA_hi + (size_t)M_ROWS * 512;

    cudaFuncSetAttribute(gemm_mma, cudaFuncAttributeMaxDynamicSharedMemorySize, GEMM_SMEM);

    const dim3 tb(32, 8);
    auto splitN = [&](const float* src, bf16* h, bf16* l, int n) {
        split_k<<<(n / 4 + 255) / 256, 256>>>(src, h, l, n / 4);
    };

    // x (B,C,L) -> xT (B,L,C), fused bf16 split
    transpose_split_k<<<dim3(SEQ / 32, CH / 32, BATCH), tb>>>(x, Ahi, Alo, CH, SEQ);

    // ---- layer 0 input gates (K=256, N=768), fwd+bwd in one launch ----
    splitN(w_ih0f, Bhi,                   Blo,                   G3 * CH);
    splitN(w_ih0b, Bhi + (size_t)G3 * CH, Blo + (size_t)G3 * CH, G3 * CH);
    gemm_mma<<<dim3(G3 / 128, M_ROWS / 128, 2), 256, GEMM_SMEM>>>(
        Ahi, Alo, Bhi, Blo, b_ih0f, b_ih0b, gi, nullptr, nullptr, G3, CH, 0, 0);

    scan_kernel<<<dim3(SPLIT, 2 * BATCH), STH>>>(
        gi, w_hh0f, b_hh0f, w_hh0b, b_hh0b, nullptr, bufA_hi, bufA_lo);

    // ---- layer 1 input gates (K=512, N=768), fwd+bwd in one launch ----
    splitN(w_ih1f, Bhi,                        Blo,                        G3 * 2 * HID);
    splitN(w_ih1b, Bhi + (size_t)G3 * 2 * HID, Blo + (size_t)G3 * 2 * HID, G3 * 2 * HID);
    gemm_mma<<<dim3(G3 / 128, M_ROWS / 128, 2), 256, GEMM_SMEM>>>(
        bufA_hi, bufA_lo, Bhi, Blo, b_ih1f, b_ih1b, gi, nullptr, nullptr, G3, 2 * HID, 0, 0);

    scan_kernel<<<dim3(SPLIT, 2 * BATCH), STH>>>(
        gi, w_hh1f, b_hh1f, w_hh1b, b_hh1b, bufB, nullptr, nullptr);

    // ---- sum dirs + LN -> bf16 split in Ahi/Alo ----
    sum_ln_kernel<<<M_ROWS / 8, 256>>>(bufB, ln_g, ln_b, Ahi, Alo);

    // ---- FFN1: relu(ln @ w1^T + b1) -> bf16 split planes ----
    splitN(w1, Bhi, Blo, 512 * CH);
    gemm_mma<<<dim3(512 / 128, M_ROWS / 128, 1), 256, GEMM_SMEM>>>(
        Ahi, Alo, Bhi, Blo, b1, b1, nullptr, bufA_hi, bufA_lo, 512, CH, 1, 0);

    // ---- FFN2: mid @ w2^T + b2 -> d_out directly, transposed (B,C,L) ----
    splitN(w2, Bhi, Blo, 256 * 512);
    gemm_mma<<<dim3(256 / 128, M_ROWS / 128, 1), 256, GEMM_SMEM>>>(
        bufA_hi, bufA_lo, Bhi, Blo, b2, b2, (float*)d_out, nullptr, nullptr, 256, 512, 0, 1);
}

// round 17
// speedup vs baseline: 1.0452x; 1.0452x over previous
#include <cuda_runtime.h>
#include <cuda_bf16.h>
#include <cstdint>

#define BATCH 16
#define CH    256
#define SEQ   2048
#define HID   256
#define G3    768
#define M_ROWS (BATCH*SEQ)

typedef unsigned long long ull;
typedef __nv_bfloat16 bf16;

__device__ __forceinline__ ull pack2(float x, float y) {
    ull r; asm("mov.b64 %0,{%1,%2};" : "=l"(r) : "f"(x), "f"(y)); return r;
}
__device__ __forceinline__ void unpack2(ull v, float& x, float& y) {
    asm("mov.b64 {%0,%1},%2;" : "=f"(x), "=f"(y) : "l"(v));
}
__device__ __forceinline__ ull fma2(ull a, ull b, ull c) {
    ull d; asm("fma.rn.f32x2 %0,%1,%2,%3;" : "=l"(d) : "l"(a), "l"(b), "l"(c)); return d;
}
__device__ __forceinline__ float fsig(float x) {
    return __fdividef(1.f, 1.f + __expf(-x));
}
__device__ __forceinline__ float ftanh(float x) {
    float t = __expf(-2.f * fabsf(x));
    return copysignf(__fdividef(1.f - t, 1.f + t), x);
}
static __device__ __forceinline__ uint32_t smem_u32(const void* p) {
    uint32_t a;
    asm("{ .reg .u64 t; cvta.to.shared.u64 t, %1; cvt.u32.u64 %0, t; }"
        : "=r"(a) : "l"(p));
    return a;
}
__device__ __forceinline__ void mbar_wait_cta(uint32_t addr, uint32_t parity) {
    asm volatile(
        "{\n\t.reg .pred P;\n\t"
        "LW_%=:\n\t"
        "mbarrier.try_wait.parity.acquire.cta.shared::cta.b64 P, [%0], %1, 0x989680;\n\t"
        "@!P bra LW_%=;\n\t}"
        :: "r"(addr), "r"(parity) : "memory");
}

// ----------------------------- scratch -------------------------------------
__device__ float g_gi  [(size_t)2 * BATCH * SEQ * G3];
__device__ float g_bufA[(size_t)BATCH * SEQ * 2 * HID];
__device__ float g_bufB[(size_t)BATCH * SEQ * 2 * HID];
__device__ bf16  g_Ahi[(size_t)M_ROWS * 512];
__device__ bf16  g_Alo[(size_t)M_ROWS * 512];
__device__ bf16  g_Bhi[(size_t)2 * G3 * 512];
__device__ bf16  g_Blo[(size_t)2 * G3 * 512];

// ----------------------------- transpose + bf16 split ----------------------
__global__ void transpose_split_k(const float* __restrict__ src,
                                  bf16* __restrict__ hi, bf16* __restrict__ lo,
                                  int D1, int D2)
{
    __shared__ float tile[32][33];
    const int b  = blockIdx.z;
    const int j0 = blockIdx.x * 32;
    const int i0 = blockIdx.y * 32;
    const float* s = src + (size_t)b * D1 * D2;
    #pragma unroll
    for (int r = 0; r < 32; r += 8)
        tile[threadIdx.y + r][threadIdx.x] =
            s[(size_t)(i0 + threadIdx.y + r) * D2 + j0 + threadIdx.x];
    __syncthreads();
    #pragma unroll
    for (int r = 0; r < 32; r += 8) {
        float v = tile[threadIdx.x][threadIdx.y + r];
        bf16 h = __float2bfloat16_rn(v);
        size_t idx = (size_t)b * D1 * D2 + (size_t)(j0 + threadIdx.y + r) * D1
                   + i0 + threadIdx.x;
        hi[idx] = h;
        lo[idx] = __float2bfloat16_rn(v - __bfloat162float(h));
    }
}

// ----------------------------- fp32 -> (hi, lo) bf16 split (weights) -------
__global__ void split_k(const float* __restrict__ in,
                        bf16* __restrict__ hi, bf16* __restrict__ lo, int n4)
{
    int i = blockIdx.x * 256 + threadIdx.x;
    if (i >= n4) return;
    float4 v = ((const float4*)in)[i];
    bf16 h0 = __float2bfloat16_rn(v.x);
    bf16 h1 = __float2bfloat16_rn(v.y);
    bf16 h2 = __float2bfloat16_rn(v.z);
    bf16 h3 = __float2bfloat16_rn(v.w);
    __nv_bfloat162* hp = (__nv_bfloat162*)hi;
    __nv_bfloat162* lp = (__nv_bfloat162*)lo;
    hp[i*2]   = __nv_bfloat162(h0, h1);
    hp[i*2+1] = __nv_bfloat162(h2, h3);
    lp[i*2]   = __nv_bfloat162(__float2bfloat16_rn(v.x - __bfloat162float(h0)),
                               __float2bfloat16_rn(v.y - __bfloat162float(h1)));
    lp[i*2+1] = __nv_bfloat162(__float2bfloat16_rn(v.z - __bfloat162float(h2)),
                               __float2bfloat16_rn(v.w - __bfloat162float(h3)));
}

// ----------------------------- bf16-split mma.sync GEMM (R13 core) ---------
// single-buffered smem, cp.async.cg loads; grid.z selects fwd/bwd weights.
// OUTMODE template: 0 = fp32 C row-major, 1 = bf16 hi/lo split, 2 = fp32
// transposed (B,N,SEQ) for final output. Templating keeps the hot modes at
// R13's register count (runtime epilogue branch cost 40 regs -> 1 CTA/SM).
#define KP 72
#define TILE_ELE (128 * KP)
#define TBYTES   (TILE_ELE * 2)
#define GEMM_SMEM (4 * TBYTES)

__device__ __forceinline__ void cp16(uint32_t s, const void* g) {
    asm volatile("cp.async.cg.shared.global [%0], [%1], 16;" :: "r"(s), "l"(g));
}
__device__ __forceinline__ void ldsm_x4(uint32_t a, uint32_t* r) {
    asm volatile("ldmatrix.sync.aligned.m8n8.x4.shared.b16 {%0,%1,%2,%3}, [%4];"
        : "=r"(r[0]), "=r"(r[1]), "=r"(r[2]), "=r"(r[3]) : "r"(a));
}
__device__ __forceinline__ void ldsm_x2(uint32_t a, uint32_t* r) {
    asm volatile("ldmatrix.sync.aligned.m8n8.x2.shared.b16 {%0,%1}, [%2];"
        : "=r"(r[0]), "=r"(r[1]) : "r"(a));
}
__device__ __forceinline__ void mma16816(float* c, const uint32_t* a, const uint32_t* b) {
    asm volatile(
        "mma.sync.aligned.m16n8k16.row.col.f32.bf16.bf16.f32 "
        "{%0,%1,%2,%3}, {%4,%5,%6,%7}, {%8,%9}, {%0,%1,%2,%3};"
        : "+f"(c[0]), "+f"(c[1]), "+f"(c[2]), "+f"(c[3])
        : "r"(a[0]), "r"(a[1]), "r"(a[2]), "r"(a[3]), "r"(b[0]), "r"(b[1]));
}

template<int OUTMODE>
__global__ void __launch_bounds__(256)
gemm_mma(const bf16* __restrict__ Ahi, const bf16* __restrict__ Alo,
         const bf16* __restrict__ BhiBase, const bf16* __restrict__ BloBase,
         const float* __restrict__ bias_f, const float* __restrict__ bias_b,
         float* __restrict__ C, bf16* __restrict__ Chi, bf16* __restrict__ Clo,
         int N, int K, int relu)
{
    extern __shared__ __align__(16) bf16 sm[];
    const int tid  = threadIdx.x;
    const int wid  = tid >> 5, lane = tid & 31;
    const int mw   = wid & 1,  nw   = wid >> 1;
    const int z    = blockIdx.z;
    const bf16* Bhi = BhiBase + (size_t)z * N * K;
    const bf16* Blo = BloBase + (size_t)z * N * K;
    const float* bias = z ? bias_b : bias_f;
    float* Cz = C ? (C + (size_t)z * M_ROWS * N) : nullptr;
    const size_t arow = (size_t)blockIdx.y * 128;
    const size_t brow = (size_t)blockIdx.x * 128;
    const uint32_t sb = smem_u32(sm);

    const int a_r = lane & 15, a_k = (lane >> 4) << 3;
    const int b_r = lane & 7,  b_k = ((lane >> 3) & 1) << 3;

    float acc[4][4][4];
    #pragma unroll
    for (int i = 0; i < 4; i++)
        #pragma unroll
        for (int j = 0; j < 4; j++)
            #pragma unroll
            for (int c = 0; c < 4; c++) acc[i][j][c] = 0.f;

    const int row  = tid >> 1;
    const int half = (tid & 1) * 32;
    const uint32_t s_off = (uint32_t)((row * KP + half) * 2);

    for (int kt = 0; kt < K; kt += 64) {
        __syncthreads();   // previous tile fully consumed
        const bf16* gA0 = Ahi + (arow + row) * (size_t)K + kt + half;
        const bf16* gA1 = Alo + (arow + row) * (size_t)K + kt + half;
        const bf16* gB0 = Bhi + (brow + row) * (size_t)K + kt + half;
        const bf16* gB1 = Blo + (brow + row) * (size_t)K + kt + half;
        const uint32_t s0 = sb + s_off;
        #pragma unroll
        for (int q = 0; q < 4; q++) {
            cp16(s0 +              q * 16, gA0 + q * 8);
            cp16(s0 +     TBYTES + q * 16, gA1 + q * 8);
            cp16(s0 + 2 * TBYTES + q * 16, gB0 + q * 8);
            cp16(s0 + 3 * TBYTES + q * 16, gB1 + q * 8);
        }
        asm volatile("cp.async.commit_group;" ::: "memory");
        asm volatile("cp.async.wait_group 0;" ::: "memory");
        __syncthreads();

        #pragma unroll
        for (int ks = 0; ks < 4; ks++) {
            const int k0 = ks * 16;
            uint32_t ah[4][4], al[4][4], bh[4][2], bl[4][2];
            #pragma unroll
            for (int i = 0; i < 4; i++) {
                uint32_t ao = sb + (uint32_t)(((mw * 64 + i * 16 + a_r) * KP + k0 + a_k) * 2);
                ldsm_x4(ao, ah[i]);
                ldsm_x4(ao + TBYTES, al[i]);
            }
            #pragma unroll
            for (int j = 0; j < 4; j++) {
                uint32_t bo = sb + (uint32_t)(2 * TBYTES + ((nw * 32 + j * 8 + b_r) * KP + k0 + b_k) * 2);
                ldsm_x2(bo, bh[j]);
                ldsm_x2(bo + TBYTES, bl[j]);
            }
            #pragma unroll
            for (int i = 0; i < 4; i++)
                #pragma unroll
                for (int j = 0; j < 4; j++) {
                    mma16816(acc[i][j], ah[i], bh[j]);
                    mma16816(acc[i][j], ah[i], bl[j]);
                    mma16816(acc[i][j], al[i], bh[j]);
                }
        }
    }

    const int g = lane >> 2, t = lane & 3;
    const int n_base = blockIdx.x * 128 + nw * 32;
    #pragma unroll
    for (int i = 0; i < 4; i++) {
        const size_t r0 = arow + (size_t)(mw * 64 + i * 16 + g);
        #pragma unroll
        for (int j = 0; j < 4; j++) {
            const int col = n_base + j * 8 + t * 2;
            const float b0 = bias[col], b1 = bias[col + 1];
            float v0 = acc[i][j][0] + b0, v1 = acc[i][j][1] + b1;
            float v2 = acc[i][j][2] + b0, v3 = acc[i][j][3] + b1;
            if (relu) {
                v0 = fmaxf(v0, 0.f); v1 = fmaxf(v1, 0.f);
                v2 = fmaxf(v2, 0.f); v3 = fmaxf(v3, 0.f);
            }
            if (OUTMODE == 1) {
                bf16 h0 = __float2bfloat16_rn(v0), h1 = __float2bfloat16_rn(v1);
                bf16 h2 = __float2bfloat16_rn(v2), h3 = __float2bfloat16_rn(v3);
                *(__nv_bfloat162*)&Chi[r0 * N + col] = __nv_bfloat162(h0, h1);
                *(__nv_bfloat162*)&Chi[(r0 + 8) * N + col] = __nv_bfloat162(h2, h3);
                *(__nv_bfloat162*)&Clo[r0 * N + col] = __nv_bfloat162(
                    __float2bfloat16_rn(v0 - __bfloat162float(h0)),
                    __float2bfloat16_rn(v1 - __bfloat162float(h1)));
                *(__nv_bfloat162*)&Clo[(r0 + 8) * N + col] = __nv_bfloat162(
                    __float2bfloat16_rn(v2 - __bfloat162float(h2)),
                    __float2bfloat16_rn(v3 - __bfloat162float(h3)));
            } else if (OUTMODE == 2) {
                // token r0 = b*SEQ + l ; write d_out[(b*N + col)*SEQ + l]
                const size_t bb = r0 >> 11, l = r0 & 2047;
                const size_t r1 = r0 + 8;
                const size_t bb2 = r1 >> 11, l2 = r1 & 2047;
                Cz[(bb * N + col)      * (size_t)SEQ + l ] = v0;
                Cz[(bb * N + col + 1)  * (size_t)SEQ + l ] = v1;
                Cz[(bb2 * N + col)     * (size_t)SEQ + l2] = v2;
                Cz[(bb2 * N + col + 1) * (size_t)SEQ + l2] = v3;
            } else {
                *(float2*)&Cz[r0 * N + col]       = make_float2(v0, v1);
                *(float2*)&Cz[(r0 + 8) * N + col] = make_float2(v2, v3);
            }
        }
    }
}

// ----------------------------- GRU scan (R10 winner, verbatim — FROZEN) ----
#define SPLIT 4
#define STH   384

__global__ void __launch_bounds__(STH, 1) __cluster_dims__(SPLIT, 1, 1)
scan_kernel(const float* __restrict__ gi,
            const float* __restrict__ whh_f, const float* __restrict__ bhh_f,
            const float* __restrict__ whh_b, const float* __restrict__ bhh_b,
            float* __restrict__ out, bf16* __restrict__ ohi, bf16* __restrict__ olo)
{
    const int ci    = blockIdx.x;
    const int chain = blockIdx.y;
    const int b     = chain & (BATCH - 1);
    const int dir   = chain >> 4;
    const float* whh = dir ? whh_b : whh_f;
    const float* bhh = dir ? bhh_b : bhh_f;
    const float* giB = gi + ((size_t)dir * BATCH + b) * (size_t)SEQ * G3;
    const size_t obase = (size_t)b * SEQ * (2 * HID) + dir * HID;

    const int tid  = threadIdx.x;
    const int g    = tid / 192;
    const int o    = tid % 192;
    const int gate = o >> 6;
    const int jl   = o & 63;
    const int row  = gate * HID + ci * 64 + jl;
    const int gu   = ci * 64 + jl;

    __shared__ __align__(16) float hbuf[2][HID];
    __shared__ float part[STH];
    __shared__ __align__(8) ull mbar[2];

    ull wreg[64];
    {
        const ull* wp = (const ull*)(whh + (size_t)row * HID + g * 128);
        #pragma unroll
        for (int i = 0; i < 64; i++) wreg[i] = wp[i];
    }
    const float bias = (g == 0) ? bhh[row] : 0.f;

    const uint32_t hb0 = smem_u32(&hbuf[0][0]);
    const uint32_t mb0 = smem_u32(&mbar[0]);

    if (tid == 0) {
        asm volatile("mbarrier.init.shared.b64 [%0], 1;" :: "r"(mb0)     : "memory");
        asm volatile("mbarrier.init.shared.b64 [%0], 1;" :: "r"(mb0 + 8) : "memory");
        asm volatile("mbarrier.arrive.expect_tx.shared.b64 _, [%0], 1024;" :: "r"(mb0)     : "memory");
        asm volatile("mbarrier.arrive.expect_tx.shared.b64 _, [%0], 1024;" :: "r"(mb0 + 8) : "memory");
    }
    for (int i = tid; i < 2 * HID; i += STH) (&hbuf[0][0])[i] = 0.f;
    __syncthreads();
    asm volatile("barrier.cluster.arrive.aligned;" ::: "memory");
    asm volatile("barrier.cluster.wait.aligned;"   ::: "memory");

    uint32_t rh0[4], rh1[4], rm0[4], rm1[4];
    if (tid < 64) {
        const uint32_t d0 = hb0 + (uint32_t)(gu * 4);
        const uint32_t d1 = hb0 + (uint32_t)((HID + gu) * 4);
        #pragma unroll
        for (int peer = 0; peer < SPLIT; peer++) {
            asm volatile("mapa.shared::cluster.u32 %0, %1, %2;" : "=r"(rh0[peer]) : "r"(d0), "r"(peer));
            asm volatile("mapa.shared::cluster.u32 %0, %1, %2;" : "=r"(rh1[peer]) : "r"(d1), "r"(peer));
            asm volatile("mapa.shared::cluster.u32 %0, %1, %2;" : "=r"(rm0[peer]) : "r"(mb0), "r"(peer));
            asm volatile("mapa.shared::cluster.u32 %0, %1, %2;" : "=r"(rm1[peer]) : "r"(mb0 + 8), "r"(peer));
        }
    }

    float hreg = 0.f;
    float p_r = 0.f, p_z = 0.f, p_n = 0.f;
    if (tid < 64) {
        const float* gp = giB + (size_t)(dir ? SEQ - 1 : 0) * G3 + gu;
        p_r = __ldg(gp); p_z = __ldg(gp + HID); p_n = __ldg(gp + 2 * HID);
    }

    int ph0 = 0, ph1 = 0;
    for (int s = 0; s < SEQ; s++) {
        const int t = dir ? (SEQ - 1 - s) : s;
        const int p = s & 1;

        if (s > 0) {
            const uint32_t mwadr = mb0 + (uint32_t)(p * 8);
            const uint32_t par = p ? (uint32_t)ph1 : (uint32_t)ph0;
            mbar_wait_cta(mwadr, par);
            if (p) ph1 ^= 1; else ph0 ^= 1;
            if (tid == 0 && s + 2 < SEQ)
                asm volatile("mbarrier.arrive.expect_tx.shared.b64 _, [%0], 1024;"
                             :: "r"(mwadr) : "memory");
        }

        const float gi_r = p_r, gi_z = p_z, gi_n = p_n;
        if (tid < 64 && s + 1 < SEQ) {
            const int tn = dir ? (SEQ - 2 - s) : (s + 1);
            const float* gp = giB + (size_t)tn * G3 + gu;
            p_r = __ldg(gp); p_z = __ldg(gp + HID); p_n = __ldg(gp + 2 * HID);
        }

        ull acc0 = pack2(bias, 0.f);
        ull acc1 = 0ull;
        const ulonglong2* h2 = (const ulonglong2*)&hbuf[p][g * 128];
        #pragma unroll
        for (int kk = 0; kk < 32; kk++) {
            ulonglong2 hv = h2[kk];
            acc0 = fma2(wreg[2*kk],     hv.x, acc0);
            acc1 = fma2(wreg[2*kk + 1], hv.y, acc1);
        }
        float aa, bb, cc, dd;
        unpack2(acc0, aa, bb); unpack2(acc1, cc, dd);
        part[tid] = (aa + cc) + (bb + dd);
        __syncthreads();

        if (tid < 64) {
            const float gh_r = part[tid]       + part[192 + tid];
            const float gh_z = part[64 + tid]  + part[256 + tid];
            const float gh_n = part[128 + tid] + part[320 + tid];
            const float r = fsig(gi_r + gh_r);
            const float z = fsig(gi_z + gh_z);
            const float n = ftanh(gi_n + r * gh_n);
            hreg = n + z * (hreg - n);
            if (s + 1 < SEQ) {
                #pragma unroll
                for (int peer = 0; peer < SPLIT; peer++) {
                    const uint32_t ra = p ? rh0[peer] : rh1[peer];
                    const uint32_t rm = p ? rm0[peer] : rm1[peer];
                    asm volatile(
                        "st.async.shared::cluster.mbarrier::complete_tx::bytes.f32 [%0], %1, [%2];"
                        :: "r"(ra), "f"(hreg), "r"(rm) : "memory");
                }
            }
            const size_t idx = obase + (size_t)t * (2 * HID) + gu;
            if (ohi) {
                bf16 h = __float2bfloat16_rn(hreg);
                ohi[idx] = h;
                olo[idx] = __float2bfloat16_rn(hreg - __bfloat162float(h));
            } else {
                out[idx] = hreg;
            }
        }
    }
}

// ----------------------------- sum dirs + LayerNorm (bf16 split out) -------
__global__ void sum_ln_kernel(const float* __restrict__ in,
                              const float* __restrict__ gw,
                              const float* __restrict__ bw,
                              bf16* __restrict__ ohi, bf16* __restrict__ olo)
{
    const int lane = threadIdx.x & 31;
    const size_t row = (size_t)blockIdx.x * 8 + (threadIdx.x >> 5);
    const float* r = in + row * 512;
    float v[8]; float s = 0.f, s2 = 0.f;
    #pragma unroll
    for (int i = 0; i < 8; i++) {
        int c = i * 32 + lane;
        v[i] = r[c] + r[256 + c];
        s += v[i]; s2 += v[i] * v[i];
    }
    #pragma unroll
    for (int off = 16; off; off >>= 1) {
        s  += __shfl_xor_sync(~0u, s,  off);
        s2 += __shfl_xor_sync(~0u, s2, off);
    }
    const float mu  = s * (1.f / 256.f);
    const float var = s2 * (1.f / 256.f) - mu * mu;
    const float inv = rsqrtf(var + 1e-5f);
    #pragma unroll
    for (int i = 0; i < 8; i++) {
        int c = i * 32 + lane;
        float y = (v[i] - mu) * inv * gw[c] + bw[c];
        bf16 h = __float2bfloat16_rn(y);
        ohi[row * 256 + c] = h;
        olo[row * 256 + c] = __float2bfloat16_rn(y - __bfloat162float(h));
    }
}

// ----------------------------- orchestration -------------------------------
extern "C" void kernel_launch(void* const* d_in, const int* in_sizes, int n_in,
                              void* d_out, int out_size)
{
    (void)in_sizes; (void)n_in; (void)out_size;
    const float* x      = (const float*)d_in[0];
    const float* w_ih0f = (const float*)d_in[1];
    const float* w_hh0f = (const float*)d_in[2];
    const float* b_ih0f = (const float*)d_in[3];
    const float* b_hh0f = (const float*)d_in[4];
    const float* w_ih0b = (const float*)d_in[5];
    const float* w_hh0b = (const float*)d_in[6];
    const float* b_ih0b = (const float*)d_in[7];
    const float* b_hh0b = (const float*)d_in[8];
    const float* w_ih1f = (const float*)d_in[9];
    const float* w_hh1f = (const float*)d_in[10];
    const float* b_ih1f = (const float*)d_in[11];
    const float* b_hh1f = (const float*)d_in[12];
    const float* w_ih1b = (const float*)d_in[13];
    const float* w_hh1b = (const float*)d_in[14];
    const float* b_ih1b = (const float*)d_in[15];
    const float* b_hh1b = (const float*)d_in[16];
    const float* ln_g   = (const float*)d_in[17];
    const float* ln_b   = (const float*)d_in[18];
    const float* w1     = (const float*)d_in[19];
    const float* b1     = (const float*)d_in[20];
    const float* w2     = (const float*)d_in[21];
    const float* b2     = (const float*)d_in[22];

    float *gi, *bufA, *bufB;
    bf16 *Ahi, *Alo, *Bhi, *Blo;
    cudaGetSymbolAddress((void**)&gi,   g_gi);
    cudaGetSymbolAddress((void**)&bufA, g_bufA);
    cudaGetSymbolAddress((void**)&bufB, g_bufB);
    cudaGetSymbolAddress((void**)&Ahi,  g_Ahi);
    cudaGetSymbolAddress((void**)&Alo,  g_Alo);
    cudaGetSymbolAddress((void**)&Bhi,  g_Bhi);
    cudaGetSymbolAddress((void**)&Blo,  g_Blo);

    bf16* bufA_hi = (bf16*)bufA;
    bf16* bufA_lo = bufA_hi + (size_t)M_ROWS * 512;

    cudaFuncSetAttribute(gemm_mma<0>, cudaFuncAttributeMaxDynamicSharedMemorySize, GEMM_SMEM);
    cudaFuncSetAttribute(gemm_mma<1>, cudaFuncAttributeMaxDynamicSharedMemorySize, GEMM_SMEM);
    cudaFuncSetAttribute(gemm_mma<2>, cudaFuncAttributeMaxDynamicSharedMemorySize, GEMM_SMEM);

    const dim3 tb(32, 8);
    auto splitN = [&](const float* src, bf16* h, bf16* l, int n) {
        split_k<<<(n / 4 + 255) / 256, 256>>>(src, h, l, n / 4);
    };

    // x (B,C,L) -> xT (B,L,C), fused bf16 split
    transpose_split_k<<<dim3(SEQ / 32, CH / 32, BATCH), tb>>>(x, Ahi, Alo, CH, SEQ);

    // ---- layer 0 input gates (K=256, N=768), fwd+bwd in one launch ----
    splitN(w_ih0f, Bhi,                   Blo,                   G3 * CH);
    splitN(w_ih0b, Bhi + (size_t)G3 * CH, Blo + (size_t)G3 * CH, G3 * CH);
    gemm_mma<0><<<dim3(G3 / 128, M_ROWS / 128, 2), 256, GEMM_SMEM>>>(
        Ahi, Alo, Bhi, Blo, b_ih0f, b_ih0b, gi, nullptr, nullptr, G3, CH, 0);

    scan_kernel<<<dim3(SPLIT, 2 * BATCH), STH>>>(
        gi, w_hh0f, b_hh0f, w_hh0b, b_hh0b, nullptr, bufA_hi, bufA_lo);

    // ---- layer 1 input gates (K=512, N=768), fwd+bwd in one launch ----
    splitN(w_ih1f, Bhi,                        Blo,                        G3 * 2 * HID);
    splitN(w_ih1b, Bhi + (size_t)G3 * 2 * HID, Blo + (size_t)G3 * 2 * HID, G3 * 2 * HID);
    gemm_mma<0><<<dim3(G3 / 128, M_ROWS / 128, 2), 256, GEMM_SMEM>>>(
        bufA_hi, bufA_lo, Bhi, Blo, b_ih1f, b_ih1b, gi, nullptr, nullptr, G3, 2 * HID, 0);

    scan_kernel<<<dim3(SPLIT, 2 * BATCH), STH>>>(
        gi, w_hh1f, b_hh1f, w_hh1b, b_hh1b, bufB, nullptr, nullptr);

    // ---- sum dirs + LN -> bf16 split in Ahi/Alo ----
    sum_ln_kernel<<<M_ROWS / 8, 256>>>(bufB, ln_g, ln_b, Ahi, Alo);

    // ---- FFN1: relu(ln @ w1^T + b1) -> bf16 split planes ----
    splitN(w1, Bhi, Blo, 512 * CH);
    gemm_mma<1><<<dim3(512 / 128, M_ROWS / 128, 1), 256, GEMM_SMEM>>>(
        Ahi, Alo, Bhi, Blo, b1, b1, nullptr, bufA_hi, bufA_lo, 512, CH, 1);

    // ---- FFN2: mid @ w2^T + b2 -> d_out directly, transposed (B,C,L) ----
    splitN(w2, Bhi, Blo, 256 * 512);
    gemm_mma<2><<<dim3(256 / 128, M_ROWS / 128, 1), 256, GEMM_SMEM>>>(
        bufA_hi, bufA_lo, Bhi, Blo, b2, b2, (float*)d_out, nullptr, nullptr, 256, 512, 0);
}